// round 2
// baseline (speedup 1.0000x reference)
#include <cuda_runtime.h>
#include <math.h>

// Problem constants (fixed by the dataset)
#define Nn 20000
#define Dd 512
#define Hh 512
#define Kk 128
#define ETOT_MAX 400000
#define BETA 100.0f
#define NITER 11          // 10 iters in first _cluster + 1 iter in second (identical body)
#define ALPHA 0.5f

// ---------------- scratch (static device allocations; no cudaMalloc) ----------------
__device__ float g_Z[Nn * Hh];      // feat @ W1
__device__ float g_T[Nn * Hh];      // Agg scratch
__device__ float g_Hb[Nn * Hh];     // hidden layer activations
__device__ float g_pos[Nn * Hh];
__device__ float g_neg[Nn * Hh];
__device__ float g_data[Nn * Hh];   // row-normalized pos
__device__ float g_dist[Nn * Kk];
__device__ float g_r[Nn * Kk];
__device__ float g_mu[Kk * Hh];
__device__ float g_muT[Hh * Kk];    // normalized mu, transposed
__device__ float g_Sk[Kk * Hh];     // r^T @ data
__device__ float g_rsum[Kk];
__device__ float g_colsum[Hh];
__device__ float g_gs[Hh];          // sigmoid(mean(pos))
__device__ float g_ws[Hh];          // disc_W @ gs
__device__ float g_acc[4];          // softplus sums: pos_g, neg_g, pos_c, neg_c
__device__ int   g_indeg[Nn];
__device__ int   g_outdeg[Nn];
__device__ int   g_offs[Nn + 1];
__device__ int   g_cursor[Nn];
__device__ int   g_csrc[ETOT_MAX];
__device__ float g_cw[ETOT_MAX];
__device__ float g_invin[Nn];
__device__ float g_invout[Nn];

// ---------------- helpers ----------------
__device__ __forceinline__ float warpSum(float v) {
    #pragma unroll
    for (int o = 16; o; o >>= 1) v += __shfl_xor_sync(0xffffffffu, v, o);
    return v;
}
__device__ __forceinline__ float warpMax(float v) {
    #pragma unroll
    for (int o = 16; o; o >>= 1) v = fmaxf(v, __shfl_xor_sync(0xffffffffu, v, o));
    return v;
}
__device__ __forceinline__ float softplusf(float x) {
    return fmaxf(x, 0.0f) + log1pf(expf(-fabsf(x)));
}
__device__ __forceinline__ float sigmoidf(float x) {
    return 1.0f / (1.0f + expf(-x));
}

// ---------------- graph preprocessing ----------------
__global__ void k_deg(const int* __restrict__ src, const int* __restrict__ dst, int E) {
    int i = blockIdx.x * blockDim.x + threadIdx.x;
    if (i < E) {
        atomicAdd(&g_outdeg[src[i]], 1);
        atomicAdd(&g_indeg[dst[i]], 1);
    }
}

__global__ void k_inv() {
    int i = blockIdx.x * blockDim.x + threadIdx.x;
    if (i < Nn) {
        g_invout[i] = rsqrtf(fmaxf((float)g_outdeg[i], 1.0f));
        g_invin[i]  = rsqrtf(fmaxf((float)g_indeg[i], 1.0f));
    }
}

// single-block exclusive scan of indeg -> offs, cursor
__global__ void k_scan() {
    __shared__ int ssum[1024];
    const int CH = 20;  // 1024 * 20 = 20480 >= Nn
    int t = threadIdx.x;
    int base = t * CH;
    int s = 0;
    for (int i = 0; i < CH; i++) {
        int idx = base + i;
        if (idx < Nn) s += g_indeg[idx];
    }
    ssum[t] = s;
    __syncthreads();
    for (int off = 1; off < 1024; off <<= 1) {
        int v = (t >= off) ? ssum[t - off] : 0;
        __syncthreads();
        ssum[t] += v;
        __syncthreads();
    }
    int run = (t > 0) ? ssum[t - 1] : 0;
    for (int i = 0; i < CH; i++) {
        int idx = base + i;
        if (idx < Nn) {
            g_offs[idx] = run;
            g_cursor[idx] = run;
            run += g_indeg[idx];
        }
    }
    if (t == 1023) g_offs[Nn] = ssum[1023];
}

__global__ void k_scatter(const int* __restrict__ src, const int* __restrict__ dst, int E) {
    int i = blockIdx.x * blockDim.x + threadIdx.x;
    if (i < E) {
        int s = src[i], d = dst[i];
        int p = atomicAdd(&g_cursor[d], 1);
        g_csrc[p] = s;
        g_cw[p] = g_invout[s];
    }
}

// ---------------- GCN aggregation: out[n] = inv_in[n] * sum_e w_e * in[idx(src_e)] ----------------
// optionally +bias, relu; optional perm indirection for the corrupted pass
__global__ void k_agg(const float4* __restrict__ in4, float4* __restrict__ out4,
                      const float* __restrict__ bias, int relu, const int* __restrict__ perm) {
    int node = blockIdx.x;
    int t = threadIdx.x;  // 128 threads, each owns 4 features
    int e = g_offs[node], e1 = g_offs[node + 1];
    float4 acc = make_float4(0.f, 0.f, 0.f, 0.f);
    for (; e < e1; e++) {
        int s = g_csrc[e];
        float w = g_cw[e];
        if (perm) s = __ldg(&perm[s]);
        float4 v = __ldg(&in4[s * (Hh / 4) + t]);
        acc.x += w * v.x; acc.y += w * v.y; acc.z += w * v.z; acc.w += w * v.w;
    }
    float sc = g_invin[node];
    acc.x *= sc; acc.y *= sc; acc.z *= sc; acc.w *= sc;
    if (bias) {
        float4 b = ((const float4*)bias)[t];
        acc.x += b.x; acc.y += b.y; acc.z += b.z; acc.w += b.w;
    }
    if (relu) {
        acc.x = fmaxf(acc.x, 0.f); acc.y = fmaxf(acc.y, 0.f);
        acc.z = fmaxf(acc.z, 0.f); acc.w = fmaxf(acc.w, 0.f);
    }
    out4[node * (Hh / 4) + t] = acc;
}

// ---------------- SGEMM: C[M,Nd] = A[M,Kd] @ B[Kd,Nd] (+bias, relu) ----------------
#define BM 128
#define BN 128
#define BKT 16
__global__ __launch_bounds__(256, 2) void k_sgemm(
    const float* __restrict__ A, const float* __restrict__ B, float* __restrict__ C,
    int M, int Kd, int Nd, const float* __restrict__ bias, int relu) {
    __shared__ float As[2][BKT][BM + 4];
    __shared__ float Bs[2][BKT][BN];
    const int tx = threadIdx.x;
    const int m0 = blockIdx.x * BM, n0 = blockIdx.y * BN;
    const int tr = tx >> 4, tc = tx & 15;
    float acc[8][8];
    #pragma unroll
    for (int i = 0; i < 8; i++)
        #pragma unroll
        for (int j = 0; j < 8; j++) acc[i][j] = 0.f;

    const int kTiles = Kd >> 4;

    // prologue load tile 0
    #pragma unroll
    for (int s2 = 0; s2 < 2; s2++) {
        int q = 2 * tx + s2;
        int ar = q >> 2, ac = q & 3;
        int gm = m0 + ar;
        float4 av = make_float4(0.f, 0.f, 0.f, 0.f);
        if (gm < M) av = *(const float4*)(A + gm * Kd + ac * 4);
        As[0][ac * 4 + 0][ar] = av.x; As[0][ac * 4 + 1][ar] = av.y;
        As[0][ac * 4 + 2][ar] = av.z; As[0][ac * 4 + 3][ar] = av.w;
        int br = q >> 5, bc = q & 31;
        float4 bv = *(const float4*)(B + br * Nd + n0 + bc * 4);
        *(float4*)(&Bs[0][br][bc * 4]) = bv;
    }
    __syncthreads();

    int buf = 0;
    for (int t = 0; t < kTiles; t++) {
        float4 pa[2], pb[2];
        if (t + 1 < kTiles) {
            int k0 = (t + 1) << 4;
            #pragma unroll
            for (int s2 = 0; s2 < 2; s2++) {
                int q = 2 * tx + s2;
                int ar = q >> 2, ac = q & 3;
                int gm = m0 + ar;
                pa[s2] = make_float4(0.f, 0.f, 0.f, 0.f);
                if (gm < M) pa[s2] = *(const float4*)(A + gm * Kd + k0 + ac * 4);
                int br = q >> 5, bc = q & 31;
                pb[s2] = *(const float4*)(B + (k0 + br) * Nd + n0 + bc * 4);
            }
        }
        #pragma unroll
        for (int kk = 0; kk < BKT; kk++) {
            float4 a0 = *(const float4*)&As[buf][kk][tr * 8];
            float4 a1 = *(const float4*)&As[buf][kk][tr * 8 + 4];
            float4 b0 = *(const float4*)&Bs[buf][kk][tc * 8];
            float4 b1 = *(const float4*)&Bs[buf][kk][tc * 8 + 4];
            float af[8] = {a0.x, a0.y, a0.z, a0.w, a1.x, a1.y, a1.z, a1.w};
            float bf[8] = {b0.x, b0.y, b0.z, b0.w, b1.x, b1.y, b1.z, b1.w};
            #pragma unroll
            for (int i = 0; i < 8; i++)
                #pragma unroll
                for (int j = 0; j < 8; j++) acc[i][j] += af[i] * bf[j];
        }
        if (t + 1 < kTiles) {
            int nb = buf ^ 1;
            #pragma unroll
            for (int s2 = 0; s2 < 2; s2++) {
                int q = 2 * tx + s2;
                int ar = q >> 2, ac = q & 3;
                As[nb][ac * 4 + 0][ar] = pa[s2].x; As[nb][ac * 4 + 1][ar] = pa[s2].y;
                As[nb][ac * 4 + 2][ar] = pa[s2].z; As[nb][ac * 4 + 3][ar] = pa[s2].w;
                int br = q >> 5, bc = q & 31;
                *(float4*)(&Bs[nb][br][bc * 4]) = pb[s2];
            }
        }
        __syncthreads();
        buf ^= 1;
    }

    float4 bq0 = make_float4(0.f, 0.f, 0.f, 0.f), bq1 = bq0;
    if (bias) {
        bq0 = *(const float4*)(bias + n0 + tc * 8);
        bq1 = *(const float4*)(bias + n0 + tc * 8 + 4);
    }
    #pragma unroll
    for (int i = 0; i < 8; i++) {
        int gm = m0 + tr * 8 + i;
        if (gm < M) {
            float4 v0 = make_float4(acc[i][0] + bq0.x, acc[i][1] + bq0.y,
                                    acc[i][2] + bq0.z, acc[i][3] + bq0.w);
            float4 v1 = make_float4(acc[i][4] + bq1.x, acc[i][5] + bq1.y,
                                    acc[i][6] + bq1.z, acc[i][7] + bq1.w);
            if (relu) {
                v0.x = fmaxf(v0.x, 0.f); v0.y = fmaxf(v0.y, 0.f);
                v0.z = fmaxf(v0.z, 0.f); v0.w = fmaxf(v0.w, 0.f);
                v1.x = fmaxf(v1.x, 0.f); v1.y = fmaxf(v1.y, 0.f);
                v1.z = fmaxf(v1.z, 0.f); v1.w = fmaxf(v1.w, 0.f);
            }
            *(float4*)(C + gm * Nd + n0 + tc * 8) = v0;
            *(float4*)(C + gm * Nd + n0 + tc * 8 + 4) = v1;
        }
    }
}

// ---------------- split-K rank-update: Sk[128,512] += r^T @ data ----------------
// grid.x = 50 splits of 400 rows, grid.y = 4 h-tiles of 128
__global__ __launch_bounds__(256, 2) void k_rtd(
    const float* __restrict__ R, const float* __restrict__ Dm, float* __restrict__ C) {
    __shared__ float Rs[2][BKT][Kk];
    __shared__ float Ds[2][BKT][128];
    const int tx = threadIdx.x;
    const int n0 = blockIdx.x * 400;
    const int h0 = blockIdx.y * 128;
    const int tr = tx >> 4, tc = tx & 15;
    float acc[8][8];
    #pragma unroll
    for (int i = 0; i < 8; i++)
        #pragma unroll
        for (int j = 0; j < 8; j++) acc[i][j] = 0.f;

    const int steps = 400 / BKT;  // 25

    #pragma unroll
    for (int s2 = 0; s2 < 2; s2++) {
        int q = 2 * tx + s2;
        int rr = q >> 5, rc = q & 31;
        *(float4*)(&Rs[0][rr][rc * 4]) = *(const float4*)(R + (n0 + rr) * Kk + rc * 4);
        *(float4*)(&Ds[0][rr][rc * 4]) = *(const float4*)(Dm + (n0 + rr) * Hh + h0 + rc * 4);
    }
    __syncthreads();

    int buf = 0;
    for (int t = 0; t < steps; t++) {
        float4 pr[2], pd[2];
        if (t + 1 < steps) {
            int nrow = n0 + (t + 1) * BKT;
            #pragma unroll
            for (int s2 = 0; s2 < 2; s2++) {
                int q = 2 * tx + s2;
                int rr = q >> 5, rc = q & 31;
                pr[s2] = *(const float4*)(R + (nrow + rr) * Kk + rc * 4);
                pd[s2] = *(const float4*)(Dm + (nrow + rr) * Hh + h0 + rc * 4);
            }
        }
        #pragma unroll
        for (int kk = 0; kk < BKT; kk++) {
            float4 a0 = *(const float4*)&Rs[buf][kk][tr * 8];
            float4 a1 = *(const float4*)&Rs[buf][kk][tr * 8 + 4];
            float4 b0 = *(const float4*)&Ds[buf][kk][tc * 8];
            float4 b1 = *(const float4*)&Ds[buf][kk][tc * 8 + 4];
            float af[8] = {a0.x, a0.y, a0.z, a0.w, a1.x, a1.y, a1.z, a1.w};
            float bf[8] = {b0.x, b0.y, b0.z, b0.w, b1.x, b1.y, b1.z, b1.w};
            #pragma unroll
            for (int i = 0; i < 8; i++)
                #pragma unroll
                for (int j = 0; j < 8; j++) acc[i][j] += af[i] * bf[j];
        }
        if (t + 1 < steps) {
            int nb = buf ^ 1;
            #pragma unroll
            for (int s2 = 0; s2 < 2; s2++) {
                int q = 2 * tx + s2;
                int rr = q >> 5, rc = q & 31;
                *(float4*)(&Rs[nb][rr][rc * 4]) = pr[s2];
                *(float4*)(&Ds[nb][rr][rc * 4]) = pd[s2];
            }
        }
        __syncthreads();
        buf ^= 1;
    }
    #pragma unroll
    for (int i = 0; i < 8; i++)
        #pragma unroll
        for (int j = 0; j < 8; j++)
            atomicAdd(&C[(tr * 8 + i) * Hh + h0 + tc * 8 + j], acc[i][j]);
}

// ---------------- clustering pieces ----------------
__global__ void k_rownorm() {  // data = pos / (||pos|| + 1e-8)
    int n = blockIdx.x, t = threadIdx.x;  // 128 threads
    __shared__ float sred[4];
    float4 p = ((const float4*)g_pos)[n * (Hh / 4) + t];
    float ss = p.x * p.x + p.y * p.y + p.z * p.z + p.w * p.w;
    float w = warpSum(ss);
    if ((t & 31) == 0) sred[t >> 5] = w;
    __syncthreads();
    float total = sred[0] + sred[1] + sred[2] + sred[3];
    float s = 1.0f / (sqrtf(total) + 1e-8f);
    p.x *= s; p.y *= s; p.z *= s; p.w *= s;
    ((float4*)g_data)[n * (Hh / 4) + t] = p;
}

__global__ void k_norm_mu() {  // muT[h][k] = mu[k][h] / ||mu[k]||
    int k = blockIdx.x, t = threadIdx.x;  // 128 blocks, 128 threads
    __shared__ float sred[4];
    float4 m = ((const float4*)g_mu)[k * (Hh / 4) + t];
    float ss = m.x * m.x + m.y * m.y + m.z * m.z + m.w * m.w;
    float w = warpSum(ss);
    if ((t & 31) == 0) sred[t >> 5] = w;
    __syncthreads();
    float total = sred[0] + sred[1] + sred[2] + sred[3];
    float s = rsqrtf(total);
    g_muT[(t * 4 + 0) * Kk + k] = m.x * s;
    g_muT[(t * 4 + 1) * Kk + k] = m.y * s;
    g_muT[(t * 4 + 2) * Kk + k] = m.z * s;
    g_muT[(t * 4 + 3) * Kk + k] = m.w * s;
}

__global__ void k_softmax() {  // r = softmax(BETA * dist) rowwise; accumulate rsum
    int warp = threadIdx.x >> 5, lane = threadIdx.x & 31;
    int node = blockIdx.x * 8 + warp;
    __shared__ float s_r[Kk];
    if (threadIdx.x < Kk) s_r[threadIdx.x] = 0.f;
    __syncthreads();
    float4 d = *(const float4*)&g_dist[node * Kk + lane * 4];
    float m = fmaxf(fmaxf(d.x, d.y), fmaxf(d.z, d.w));
    m = warpMax(m);
    float e0 = expf(BETA * (d.x - m));
    float e1 = expf(BETA * (d.y - m));
    float e2 = expf(BETA * (d.z - m));
    float e3 = expf(BETA * (d.w - m));
    float sum = warpSum(e0 + e1 + e2 + e3);
    float inv = 1.0f / sum;
    float4 r = make_float4(e0 * inv, e1 * inv, e2 * inv, e3 * inv);
    *(float4*)&g_r[node * Kk + lane * 4] = r;
    atomicAdd(&s_r[lane * 4 + 0], r.x);
    atomicAdd(&s_r[lane * 4 + 1], r.y);
    atomicAdd(&s_r[lane * 4 + 2], r.z);
    atomicAdd(&s_r[lane * 4 + 3], r.w);
    __syncthreads();
    if (threadIdx.x < Kk) atomicAdd(&g_rsum[threadIdx.x], s_r[threadIdx.x]);
}

__global__ void k_muupd() {  // mu = Sk / rsum
    int idx = blockIdx.x * blockDim.x + threadIdx.x;
    if (idx < Kk * Hh) g_mu[idx] = g_Sk[idx] / g_rsum[idx >> 9];
}

// ---------------- summaries & discriminators ----------------
__global__ void k_colsum() {  // colsum += column sums of pos (per-block partial)
    int rb = blockIdx.x * 125;  // 160 * 125 = 20000
    int t = threadIdx.x;        // 256 threads
    float c0 = 0.f, c1 = 0.f;
    for (int r = rb; r < rb + 125; r++) {
        c0 += g_pos[r * Hh + t];
        c1 += g_pos[r * Hh + t + 256];
    }
    atomicAdd(&g_colsum[t], c0);
    atomicAdd(&g_colsum[t + 256], c1);
}

__global__ void k_gs() {  // gs = sigmoid(colsum / N)
    int t = threadIdx.x;  // 512 threads
    g_gs[t] = sigmoidf(g_colsum[t] / (float)Nn);
}

__global__ void k_ws(const float* __restrict__ dW) {  // ws = disc_W @ gs
    int warp = threadIdx.x >> 5, lane = threadIdx.x & 31;
    int row = blockIdx.x * 8 + warp;  // 64 blocks * 8 warps = 512
    float s = 0.f;
    #pragma unroll
    for (int i = 0; i < 16; i++) {
        int h = lane + 32 * i;
        s += dW[row * Hh + h] * g_gs[h];
    }
    s = warpSum(s);
    if (lane == 0) g_ws[row] = s;
}

__global__ void k_gdisc() {  // softplus sums of pos@ws and neg@ws
    int warp = threadIdx.x >> 5, lane = threadIdx.x & 31;
    int node = blockIdx.x * 8 + warp;
    __shared__ float sp, sq;
    if (threadIdx.x == 0) { sp = 0.f; sq = 0.f; }
    __syncthreads();
    float p = 0.f, q = 0.f;
    #pragma unroll
    for (int i = 0; i < 16; i++) {
        int h = lane + 32 * i;
        float w = g_ws[h];
        p += g_pos[node * Hh + h] * w;
        q += g_neg[node * Hh + h] * w;
    }
    p = warpSum(p);
    q = warpSum(q);
    if (lane == 0) {
        atomicAdd(&sp, softplusf(-p));
        atomicAdd(&sq, softplusf(q));
    }
    __syncthreads();
    if (threadIdx.x == 0) {
        atomicAdd(&g_acc[0], sp);
        atomicAdd(&g_acc[1], sq);
    }
}

// fused: v = r[n] @ mu; s = sigmoid(v); pos_c = pos[n].s, neg_c = neg[n].s; softplus sums
__global__ void k_cdisc() {  // grid 2500, 128 threads, 8 nodes/block
    int t = threadIdx.x;
    int nb = blockIdx.x * 8;
    __shared__ float rs[8][Kk];
    __shared__ float s_p[8][4], s_n[8][4];
    #pragma unroll
    for (int j = 0; j < 8; j++) rs[j][t] = g_r[(nb + j) * Kk + t];
    __syncthreads();
    float4 v[8];
    #pragma unroll
    for (int j = 0; j < 8; j++) v[j] = make_float4(0.f, 0.f, 0.f, 0.f);
    const float4* mu4 = (const float4*)g_mu;
    for (int k = 0; k < Kk; k++) {
        float4 m = __ldg(&mu4[k * (Hh / 4) + t]);
        #pragma unroll
        for (int j = 0; j < 8; j++) {
            float rv = rs[j][k];
            v[j].x += rv * m.x; v[j].y += rv * m.y;
            v[j].z += rv * m.z; v[j].w += rv * m.w;
        }
    }
    int lane = t & 31, wid = t >> 5;
    #pragma unroll
    for (int j = 0; j < 8; j++) {
        float4 sg = make_float4(sigmoidf(v[j].x), sigmoidf(v[j].y),
                                sigmoidf(v[j].z), sigmoidf(v[j].w));
        float4 p = ((const float4*)g_pos)[(nb + j) * (Hh / 4) + t];
        float4 ng = ((const float4*)g_neg)[(nb + j) * (Hh / 4) + t];
        float pc = sg.x * p.x + sg.y * p.y + sg.z * p.z + sg.w * p.w;
        float nc = sg.x * ng.x + sg.y * ng.y + sg.z * ng.z + sg.w * ng.w;
        pc = warpSum(pc);
        nc = warpSum(nc);
        if (lane == 0) { s_p[j][wid] = pc; s_n[j][wid] = nc; }
    }
    __syncthreads();
    if (t < 8) {
        float P = s_p[t][0] + s_p[t][1] + s_p[t][2] + s_p[t][3];
        float Q = s_n[t][0] + s_n[t][1] + s_n[t][2] + s_n[t][3];
        atomicAdd(&g_acc[2], softplusf(-P));
        atomicAdd(&g_acc[3], softplusf(Q));
    }
}

__global__ void k_final(float* out) {
    if (threadIdx.x == 0) {
        float l = ALPHA * ((g_acc[0] + g_acc[1]) / (float)Nn) +
                  (1.0f - ALPHA) * ((g_acc[2] + g_acc[3]) / (float)Nn);
        out[0] = l;
    }
}

// ---------------- host launcher ----------------
extern "C" void kernel_launch(void* const* d_in, const int* in_sizes, int n_in,
                              void* d_out, int out_size) {
    const float* feat  = (const float*)d_in[0];
    const float* W1    = (const float*)d_in[1];
    const float* b1    = (const float*)d_in[2];
    const float* W2    = (const float*)d_in[3];
    const float* b2    = (const float*)d_in[4];
    const float* dW    = (const float*)d_in[5];
    const float* cinit = (const float*)d_in[6];
    const int*   eidx  = (const int*)d_in[7];
    const int*   perm  = (const int*)d_in[8];
    const int E = in_sizes[7] / 2;
    const int* src = eidx;
    const int* dst = eidx + E;

    void *pZ, *pT, *pHb, *pPos, *pNeg, *pData, *pDist, *pR, *pMu, *pMuT, *pSk,
         *pRsum, *pColsum, *pAcc, *pIndeg, *pOutdeg;
    cudaGetSymbolAddress(&pZ, g_Z);
    cudaGetSymbolAddress(&pT, g_T);
    cudaGetSymbolAddress(&pHb, g_Hb);
    cudaGetSymbolAddress(&pPos, g_pos);
    cudaGetSymbolAddress(&pNeg, g_neg);
    cudaGetSymbolAddress(&pData, g_data);
    cudaGetSymbolAddress(&pDist, g_dist);
    cudaGetSymbolAddress(&pR, g_r);
    cudaGetSymbolAddress(&pMu, g_mu);
    cudaGetSymbolAddress(&pMuT, g_muT);
    cudaGetSymbolAddress(&pSk, g_Sk);
    cudaGetSymbolAddress(&pRsum, g_rsum);
    cudaGetSymbolAddress(&pColsum, g_colsum);
    cudaGetSymbolAddress(&pAcc, g_acc);
    cudaGetSymbolAddress(&pIndeg, g_indeg);
    cudaGetSymbolAddress(&pOutdeg, g_outdeg);

    // --- graph preprocessing ---
    cudaMemsetAsync(pIndeg, 0, Nn * sizeof(int));
    cudaMemsetAsync(pOutdeg, 0, Nn * sizeof(int));
    k_deg<<<(E + 255) / 256, 256>>>(src, dst, E);
    k_inv<<<(Nn + 255) / 256, 256>>>();
    k_scan<<<1, 1024>>>();
    k_scatter<<<(E + 255) / 256, 256>>>(src, dst, E);

    dim3 gNN(157, 4);   // 20000/128 ceil x 512/128
    dim3 gNK(157, 1);   // Ncols = 128
    dim3 gRtd(50, 4);

    // --- encoder: shared first GEMM Z = feat @ W1 ---
    k_sgemm<<<gNN, 256>>>(feat, W1, (float*)pZ, Nn, Dd, Hh, nullptr, 0);
    // pos path
    k_agg<<<Nn, 128>>>((const float4*)pZ, (float4*)pHb, b1, 1, nullptr);
    k_agg<<<Nn, 128>>>((const float4*)pHb, (float4*)pT, nullptr, 0, nullptr);
    k_sgemm<<<gNN, 256>>>((const float*)pT, W2, (float*)pPos, Nn, Hh, Hh, b2, 0);
    // neg path (perm folded into layer-1 gather)
    k_agg<<<Nn, 128>>>((const float4*)pZ, (float4*)pHb, b1, 1, perm);
    k_agg<<<Nn, 128>>>((const float4*)pHb, (float4*)pT, nullptr, 0, nullptr);
    k_sgemm<<<gNN, 256>>>((const float*)pT, W2, (float*)pNeg, Nn, Hh, Hh, b2, 0);

    // --- clustering: 11 identical iterations ---
    k_rownorm<<<Nn, 128>>>();
    cudaMemcpyAsync(pMu, cinit, Kk * Hh * sizeof(float), cudaMemcpyDeviceToDevice);
    for (int it = 0; it < NITER; it++) {
        k_norm_mu<<<Kk, 128>>>();
        k_sgemm<<<gNK, 256>>>((const float*)pData, (const float*)pMuT, (float*)pDist,
                              Nn, Hh, Kk, nullptr, 0);
        cudaMemsetAsync(pRsum, 0, Kk * sizeof(float));
        k_softmax<<<2500, 256>>>();
        cudaMemsetAsync(pSk, 0, Kk * Hh * sizeof(float));
        k_rtd<<<gRtd, 256>>>((const float*)pR, (const float*)pData, (float*)pSk);
        k_muupd<<<(Kk * Hh + 255) / 256, 256>>>();
    }

    // --- summaries + discriminators ---
    cudaMemsetAsync(pColsum, 0, Hh * sizeof(float));
    cudaMemsetAsync(pAcc, 0, 4 * sizeof(float));
    k_colsum<<<160, 256>>>();
    k_gs<<<1, 512>>>();
    k_ws<<<64, 256>>>(dW);
    k_gdisc<<<2500, 256>>>();
    k_cdisc<<<2500, 128>>>();
    k_final<<<1, 32>>>((float*)d_out);
}